// round 1
// baseline (speedup 1.0000x reference)
#include <cuda_runtime.h>
#include <math.h>

// Problem constants (from reference): x (B=32, C=256, H=64, W=64) fp32
// s = mean_c(x); h = relu(s*w1 + b1) [16]; scale = sigmoid(w2 @ h + b2); out = x*scale
#define B_   32
#define CH   256
#define HW   4096      // 64*64, contiguous per (b,c)
#define HID  16
#define P    128       // pixels per block tile
#define TPB  512       // threads per block
#define CG   (TPB / P) // 4 channel groups
#define CPT  (CH / CG) // 64 channels per thread

// smem layout (floats)
#define OFF_TILE 0
#define OFF_W2   (OFF_TILE + CH * P)          // 32768
#define OFF_H    (OFF_W2 + CH * HID)          // 36864
#define OFF_RED  (OFF_H + HID * P)            // 38912
#define OFF_B2   (OFF_RED + TPB)              // 39424
#define OFF_W1   (OFF_B2 + CH)                // 39680
#define OFF_B1   (OFF_W1 + HID)               // 39696
#define SMEM_FLOATS (OFF_B1 + HID)            // 39712
#define SMEM_BYTES  (SMEM_FLOATS * 4)         // 158848

__global__ __launch_bounds__(TPB, 1)
void pse_fused_kernel(const float* __restrict__ x,
                      const float* __restrict__ w1,
                      const float* __restrict__ b1,
                      const float* __restrict__ w2,
                      const float* __restrict__ b2,
                      float* __restrict__ out)
{
    extern __shared__ float sm[];
    float* tile = sm + OFF_TILE;   // [CH][P]
    float* w2s  = sm + OFF_W2;     // [CH][HID]
    float* hs   = sm + OFF_H;      // [HID][P]
    float* red  = sm + OFF_RED;    // [TPB]
    float* b2s  = sm + OFF_B2;     // [CH]
    float* w1s  = sm + OFF_W1;     // [HID]
    float* b1s  = sm + OFF_B1;     // [HID]

    const int t   = threadIdx.x;
    const int p   = t & (P - 1);   // pixel within tile
    const int g   = t >> 7;        // channel group 0..3

    const int tile_id = blockIdx.x;        // 1024 tiles
    const int b    = tile_id >> 5;         // 32 tiles per image (4096/128)
    const int base = (tile_id & 31) << 7;  // pixel base within image

    const float* xb = x + (b * CH) * HW + base;

    // stage small params into smem (overlapped with x loads below in issue order)
    for (int i = t; i < CH * HID; i += TPB) w2s[i] = w2[i];
    if (t < CH)  b2s[t] = b2[t];
    if (t < HID) { w1s[t] = w1[t]; b1s[t] = b1[t]; }

    // ---- Pass 1: load x tile (coalesced), stash in smem, partial channel-sum ----
    float sum = 0.f;
    #pragma unroll 8
    for (int i = 0; i < CPT; i++) {
        const int c = g + i * CG;
        const float v = xb[c * HW + p];
        tile[c * P + p] = v;
        sum += v;
    }
    red[t] = sum;
    __syncthreads();

    // ---- reduce 4 partials -> mean; compute 16 hidden relu values per pixel ----
    if (t < P) {
        const float s = (red[t] + red[t + P] + red[t + 2 * P] + red[t + 3 * P])
                        * (1.0f / (float)CH);
        #pragma unroll
        for (int k = 0; k < HID; k++) {
            const float hk = fmaxf(fmaf(s, w1s[k], b1s[k]), 0.0f);
            hs[k * P + t] = hk;
        }
    }
    __syncthreads();

    // ---- Pass 2: scale = sigmoid(w2 @ h + b2); out = x * scale ----
    float* ob = out + (b * CH) * HW + base;
    #pragma unroll 4
    for (int i = 0; i < CPT; i++) {
        const int c = g + i * CG;
        float z = b2s[c];
        #pragma unroll
        for (int k = 0; k < HID; k++)
            z = fmaf(w2s[c * HID + k], hs[k * P + p], z);  // w2s: warp-broadcast
        const float sc = 1.0f / (1.0f + __expf(-z));
        ob[c * HW + p] = tile[c * P + p] * sc;
    }
}

extern "C" void kernel_launch(void* const* d_in, const int* in_sizes, int n_in,
                              void* d_out, int out_size)
{
    const float* x  = (const float*)d_in[0];
    const float* w1 = (const float*)d_in[1];
    const float* b1 = (const float*)d_in[2];
    const float* w2 = (const float*)d_in[3];
    const float* b2 = (const float*)d_in[4];
    float* out = (float*)d_out;

    // >48KB dynamic smem requires opting in (idempotent; safe under graph capture)
    cudaFuncSetAttribute(pse_fused_kernel,
                         cudaFuncAttributeMaxDynamicSharedMemorySize, SMEM_BYTES);

    const int n_tiles = (B_ * HW) / P;  // 1024
    pse_fused_kernel<<<n_tiles, TPB, SMEM_BYTES>>>(x, w1, b1, w2, b2, out);
}

// round 2
// speedup vs baseline: 1.7387x; 1.7387x over previous
#include <cuda_runtime.h>
#include <math.h>

// x (B=32, C=256, H=64, W=64) fp32; s=mean_c(x); h=relu(s*w1+b1)[16];
// scale=sigmoid(w2@h+b2); out=x*scale
// Key identity: z[c] = w2[c]@relu(s*w1+b1)+b2[c] is piecewise-linear in s:
//   z[c] = A[c,i]*s + B[c,i],  i = #{k : s > t_k},  t_k = -b1[k]/w1[k]
#define B_    32
#define CH    256
#define HW    4096
#define HW4   1024          // HW / 4 (float4)
#define HID   16
#define P     128           // pixels per tile
#define P4    32            // float4 pixels per tile
#define TPB   512
#define NGRP  16            // TPB / P4 channel groups
#define CPT   16            // CH / NGRP channels per thread
#define NTILE ((B_ * HW) / P)   // 1024
#define GRID  152           // GB300 SM count; persistent blocks

// smem layout in floats
#define OFF_TILE 0                         // [CH][P4] float4 = 32768 floats
#define OFF_AB   (OFF_TILE + CH * P4 * 4)  // 32768: [CH*17] float2 = 8704 floats
#define OFF_RED  (OFF_AB + CH * 17 * 2)    // 41472: [NGRP][P4] float4 = 2048 floats
#define OFF_US   (OFF_RED + NGRP * P4 * 4) // 43520: 16 sorted thresholds
#define OFF_REPS (OFF_US + 16)             // 43536: 17 interval representatives
#define OFF_S4   (OFF_REPS + 20)           // 43556: [P4] float4 (16B aligned)
#define OFF_I4   (OFF_S4 + P4 * 4)         // 43684: [P4] int4
#define SMEM_FLOATS (OFF_I4 + P4 * 4)      // 43812
#define SMEM_BYTES  (SMEM_FLOATS * 4)      // 175248

__global__ __launch_bounds__(TPB, 1)
void pse_fused_kernel(const float4* __restrict__ x,
                      const float* __restrict__ w1,
                      const float* __restrict__ b1,
                      const float* __restrict__ w2,
                      const float* __restrict__ b2,
                      float4* __restrict__ out)
{
    extern __shared__ float sm[];
    float4* tile = (float4*)(sm + OFF_TILE);   // [CH][P4]
    float2* AB   = (float2*)(sm + OFF_AB);     // [CH*17]
    float4* red4 = (float4*)(sm + OFF_RED);    // [NGRP][P4]
    float*  us   = sm + OFF_US;                // sorted thresholds
    float*  reps = sm + OFF_REPS;              // interval representatives
    float4* s4b  = (float4*)(sm + OFF_S4);     // per-pixel s (packed by 4)
    int4*   i4b  = (int4*)(sm + OFF_I4);       // per-pixel interval idx

    const int t = threadIdx.x;
    const int q = t & (P4 - 1);  // float4-pixel index 0..31
    const int g = t >> 5;        // channel group 0..15

    const float INF = __int_as_float(0x7f800000);

    // ---------- prologue: build piecewise-linear table ----------
    if (t < HID) {
        float w = w1[t], b = b1[t];
        float myth = (w != 0.0f) ? (-b / w) : INF;
        int rank = 0;
        #pragma unroll
        for (int k = 0; k < HID; k++) {
            float wk = w1[k], bk = b1[k];
            float tk = (wk != 0.0f) ? (-bk / wk) : INF;
            rank += (tk < myth) || (tk == myth && k < t);
        }
        us[rank] = myth;
    }
    __syncthreads();
    if (t < HID + 1) {
        float lo = (t == 0)   ? -INF : us[t - 1];
        float hi = (t == HID) ?  INF : us[t];
        bool flo = isfinite(lo), fhi = isfinite(hi);
        if (!flo && !fhi)      { lo = -1.0f; hi = 1.0f; }
        else if (!flo)         lo = hi - 2.0f;
        else if (!fhi)         hi = lo + 2.0f;
        reps[t] = 0.5f * (lo + hi);
    }
    __syncthreads();
    for (int e = t; e < CH * 17; e += TPB) {
        int c = e / 17, i = e - c * 17;
        float rep = reps[i];
        float a = 0.0f, bb = b2[c];
        #pragma unroll
        for (int k = 0; k < HID; k++) {
            float wk = w1[k], bk = b1[k];
            if (fmaf(rep, wk, bk) > 0.0f) {   // is hidden unit k active here?
                float wv = w2[c * HID + k];
                a  = fmaf(wv, wk, a);
                bb = fmaf(wv, bk, bb);
            }
        }
        AB[e] = make_float2(a, bb);
    }
    __syncthreads();

    // ---------- persistent loop over tiles ----------
    for (int tileid = blockIdx.x; tileid < NTILE; tileid += gridDim.x) {
        const int img   = tileid >> 5;
        const int base4 = (tileid & 31) << 5;   // float4 offset within image
        const float4* xb = x   + (size_t)img * CH * HW4 + base4;
        float4*       ob = out + (size_t)img * CH * HW4 + base4;

        // pass 1: coalesced float4 loads -> smem tile + per-thread pixel sums
        float4 s4 = make_float4(0.f, 0.f, 0.f, 0.f);
        #pragma unroll
        for (int j = 0; j < CPT; j++) {
            int c = g + j * NGRP;
            float4 v = xb[c * HW4 + q];
            tile[c * P4 + q] = v;
            s4.x += v.x; s4.y += v.y; s4.z += v.z; s4.w += v.w;
        }
        red4[g * P4 + q] = s4;
        __syncthreads();

        // reduce 16 groups -> mean; classify each pixel into its interval
        if (t < P4) {
            float4 acc = red4[t];
            #pragma unroll
            for (int g2 = 1; g2 < NGRP; g2++) {
                float4 r = red4[g2 * P4 + t];
                acc.x += r.x; acc.y += r.y; acc.z += r.z; acc.w += r.w;
            }
            const float inv = 1.0f / (float)CH;
            float4 sv = make_float4(acc.x*inv, acc.y*inv, acc.z*inv, acc.w*inv);
            int4 iv = make_int4(0, 0, 0, 0);
            #pragma unroll
            for (int k = 0; k < HID; k++) {
                float tk = us[k];
                iv.x += (sv.x > tk); iv.y += (sv.y > tk);
                iv.z += (sv.z > tk); iv.w += (sv.w > tk);
            }
            s4b[t] = sv; i4b[t] = iv;
        }
        __syncthreads();

        // pass 2: z = A*s+B, out = x * sigmoid(z)  (1 FFMA + exp + div per elem)
        const float4 sv = s4b[q];
        const int4   iv = i4b[q];
        #pragma unroll
        for (int j = 0; j < CPT; j++) {
            int c = g + j * NGRP;
            float4 v = tile[c * P4 + q];
            const float2* abc = AB + c * 17;
            float2 a0 = abc[iv.x], a1 = abc[iv.y], a2 = abc[iv.z], a3 = abc[iv.w];
            float z0 = fmaf(a0.x, sv.x, a0.y);
            float z1 = fmaf(a1.x, sv.y, a1.y);
            float z2 = fmaf(a2.x, sv.z, a2.y);
            float z3 = fmaf(a3.x, sv.w, a3.y);
            float4 o;
            o.x = __fdividef(v.x, 1.0f + __expf(-z0));
            o.y = __fdividef(v.y, 1.0f + __expf(-z1));
            o.z = __fdividef(v.z, 1.0f + __expf(-z2));
            o.w = __fdividef(v.w, 1.0f + __expf(-z3));
            ob[c * HW4 + q] = o;
        }
        // no trailing barrier needed: every thread re-reads only slots it
        // itself wrote (tile/red4), and s4b/i4b writes sit behind the next
        // iteration's __syncthreads.
    }
}

extern "C" void kernel_launch(void* const* d_in, const int* in_sizes, int n_in,
                              void* d_out, int out_size)
{
    const float4* x  = (const float4*)d_in[0];
    const float*  w1 = (const float*)d_in[1];
    const float*  b1 = (const float*)d_in[2];
    const float*  w2 = (const float*)d_in[3];
    const float*  b2 = (const float*)d_in[4];
    float4* out = (float4*)d_out;

    cudaFuncSetAttribute(pse_fused_kernel,
                         cudaFuncAttributeMaxDynamicSharedMemorySize, SMEM_BYTES);

    pse_fused_kernel<<<GRID, TPB, SMEM_BYTES>>>(x, w1, b1, w2, b2, out);
}

// round 3
// speedup vs baseline: 1.8613x; 1.0705x over previous
#include <cuda_runtime.h>
#include <math.h>

// x (B=32, C=256, H=64, W=64) fp32; s=mean_c(x); h=relu(s*w1+b1)[16];
// scale=sigmoid(w2@h+b2); out=x*scale
// Identity: z[c] = w2[c]@relu(s*w1+b1)+b2[c] is piecewise-linear in s:
//   z[c] = A[c,i]*s + B[c,i],  i = #{k : s > t_k},  t_k = -b1[k]/w1[k]
// Round-3 design: no x tile in smem. Pass 1 computes channel means (x read from
// DRAM), pass 2 re-reads x (guaranteed L2 hit: in-flight working set ~50MB vs
// 126MB L2). Tiny CTAs (256 thr, ~5KB smem, <=64 regs) -> 4-6 CTAs/SM.

#define B_    32
#define CH    256
#define HW4   1024          // 4096/4 float4 per (b,c) row
#define HID   16
#define P4    16            // float4 pixels per tile (64 px)
#define TPB   256
#define NGRP  16            // TPB / P4 channel groups
#define CPT   16            // CH / NGRP channels per thread
#define NTILE 2048          // 32 images * 64 tiles

__device__ float2 g_AB[CH * 17];
__device__ float  g_us[HID];

__global__ void build_table_kernel(const float* __restrict__ w1,
                                   const float* __restrict__ b1,
                                   const float* __restrict__ w2,
                                   const float* __restrict__ b2)
{
    __shared__ float us[HID];
    __shared__ float reps[HID + 1];
    const int t = threadIdx.x;
    const float INF = __int_as_float(0x7f800000);

    if (t < HID) {
        float w = w1[t], b = b1[t];
        float myth = (w != 0.0f) ? (-b / w) : INF;
        int rank = 0;
        #pragma unroll
        for (int k = 0; k < HID; k++) {
            float wk = w1[k], bk = b1[k];
            float tk = (wk != 0.0f) ? (-bk / wk) : INF;
            rank += (tk < myth) || (tk == myth && k < t);
        }
        us[rank] = myth;
    }
    __syncthreads();
    if (t < HID + 1) {
        float lo = (t == 0)   ? -INF : us[t - 1];
        float hi = (t == HID) ?  INF : us[t];
        bool flo = isfinite(lo), fhi = isfinite(hi);
        if (!flo && !fhi)      { lo = -1.0f; hi = 1.0f; }
        else if (!flo)         lo = hi - 2.0f;
        else if (!fhi)         hi = lo + 2.0f;
        reps[t] = 0.5f * (lo + hi);
    }
    __syncthreads();
    if (t < HID) g_us[t] = us[t];
    for (int e = t; e < CH * 17; e += blockDim.x) {
        int c = e / 17, i = e - c * 17;
        float rep = reps[i];
        float a = 0.0f, bb = b2[c];
        #pragma unroll
        for (int k = 0; k < HID; k++) {
            float wk = w1[k], bk = b1[k];
            if (fmaf(rep, wk, bk) > 0.0f) {      // hidden unit k active on interval i?
                float wv = w2[c * HID + k];
                a  = fmaf(wv, wk, a);
                bb = fmaf(wv, bk, bb);
            }
        }
        g_AB[e] = make_float2(a, bb);
    }
}

__global__ __launch_bounds__(TPB, 4)
void pse_main_kernel(const float4* __restrict__ x, float4* __restrict__ out)
{
    __shared__ float4 red4[NGRP * P4];   // 4 KB
    __shared__ float4 s4b[P4];
    __shared__ int4   i4b[P4];

    const int t = threadIdx.x;
    const int q = t & (P4 - 1);          // float4-pixel 0..15
    const int g = t >> 4;                // channel group 0..15

    const int tile  = blockIdx.x;
    const int img   = tile >> 6;         // 64 tiles per image
    const int base4 = (tile & 63) << 4;

    const float4* xb = x   + (size_t)img * CH * HW4 + base4;
    float4*       ob = out + (size_t)img * CH * HW4 + base4;

    // ---- pass 1: channel-partial sums (x: DRAM read, fills L2) ----
    float4 s = make_float4(0.f, 0.f, 0.f, 0.f);
    #pragma unroll 8
    for (int j = 0; j < CPT; j++) {
        const float4 v = __ldg(&xb[(g + j * NGRP) * HW4 + q]);
        s.x += v.x; s.y += v.y; s.z += v.z; s.w += v.w;
    }
    red4[g * P4 + q] = s;
    __syncthreads();

    // ---- reduce + interval classification (16 threads) ----
    if (t < P4) {
        float4 acc = red4[t];
        #pragma unroll
        for (int g2 = 1; g2 < NGRP; g2++) {
            float4 r = red4[g2 * P4 + t];
            acc.x += r.x; acc.y += r.y; acc.z += r.z; acc.w += r.w;
        }
        const float inv = 1.0f / (float)CH;
        float4 sv = make_float4(acc.x * inv, acc.y * inv, acc.z * inv, acc.w * inv);
        int4 iv = make_int4(0, 0, 0, 0);
        #pragma unroll
        for (int k = 0; k < HID; k++) {
            const float tk = g_us[k];
            iv.x += (sv.x > tk); iv.y += (sv.y > tk);
            iv.z += (sv.z > tk); iv.w += (sv.w > tk);
        }
        s4b[t] = sv; i4b[t] = iv;
    }
    __syncthreads();

    // ---- pass 2: re-read x (L2 hit), z = A*s+B, out = x*sigmoid(z) ----
    const float4 sv = s4b[q];
    const int4   iv = i4b[q];
    #pragma unroll 4
    for (int j = 0; j < CPT; j++) {
        const int c = g + j * NGRP;
        const float4 v = __ldg(&xb[c * HW4 + q]);
        const float2* row = g_AB + c * 17;      // 34KB table: L1-resident
        const float2 a0 = row[iv.x], a1 = row[iv.y],
                     a2 = row[iv.z], a3 = row[iv.w];
        const float z0 = fmaf(a0.x, sv.x, a0.y);
        const float z1 = fmaf(a1.x, sv.y, a1.y);
        const float z2 = fmaf(a2.x, sv.z, a2.y);
        const float z3 = fmaf(a3.x, sv.w, a3.y);
        float4 o;
        o.x = __fdividef(v.x, 1.0f + __expf(-z0));
        o.y = __fdividef(v.y, 1.0f + __expf(-z1));
        o.z = __fdividef(v.z, 1.0f + __expf(-z2));
        o.w = __fdividef(v.w, 1.0f + __expf(-z3));
        ob[c * HW4 + q] = o;
    }
}

extern "C" void kernel_launch(void* const* d_in, const int* in_sizes, int n_in,
                              void* d_out, int out_size)
{
    const float*  w1 = (const float*)d_in[1];
    const float*  b1 = (const float*)d_in[2];
    const float*  w2 = (const float*)d_in[3];
    const float*  b2 = (const float*)d_in[4];

    build_table_kernel<<<1, 256>>>(w1, b1, w2, b2);
    pse_main_kernel<<<NTILE, TPB>>>((const float4*)d_in[0], (float4*)d_out);
}

// round 4
// speedup vs baseline: 1.8736x; 1.0066x over previous
#include <cuda_runtime.h>
#include <math.h>

// x (B=32, C=256, H=64, W=64) fp32; s=mean_c(x); h=relu(s*w1+b1)[16];
// scale=sigmoid(w2@h+b2); out=x*scale
// Identity: z[c] = w2[c]@relu(s*w1+b1)+b2[c] is piecewise-linear in s:
//   z[c] = A[c,i]*s + B[c,i],  i = #{k : s > t_k},  t_k = -b1[k]/w1[k]
// R4: PDL overlaps the table-build launch with the main kernel's pass 1;
// 6 CTAs/SM; streaming cache hints on pass-2 read + store.

#define B_    32
#define CH    256
#define HW4   1024          // 4096/4 float4 per (b,c) row
#define HID   16
#define P4    16            // float4 pixels per tile (64 px)
#define TPB   256
#define NGRP  16            // TPB / P4 channel groups
#define CPT   16            // CH / NGRP channels per thread
#define NTILE 2048          // 32 images * 64 tiles

__device__ float2 g_AB[CH * 17];
__device__ float  g_us[HID];

__global__ void build_table_kernel(const float* __restrict__ w1,
                                   const float* __restrict__ b1,
                                   const float* __restrict__ w2,
                                   const float* __restrict__ b2)
{
    // Let the dependent (main) kernel begin immediately; it only consumes
    // g_us/g_AB after cudaGridDependencySynchronize().
    cudaTriggerProgrammaticLaunchCompletion();

    __shared__ float us[HID];
    __shared__ float reps[HID + 1];
    const int t = threadIdx.x;
    const float INF = __int_as_float(0x7f800000);

    if (t < HID) {
        float w = w1[t], b = b1[t];
        float myth = (w != 0.0f) ? (-b / w) : INF;
        int rank = 0;
        #pragma unroll
        for (int k = 0; k < HID; k++) {
            float wk = w1[k], bk = b1[k];
            float tk = (wk != 0.0f) ? (-bk / wk) : INF;
            rank += (tk < myth) || (tk == myth && k < t);
        }
        us[rank] = myth;
    }
    __syncthreads();
    if (t < HID + 1) {
        float lo = (t == 0)   ? -INF : us[t - 1];
        float hi = (t == HID) ?  INF : us[t];
        bool flo = isfinite(lo), fhi = isfinite(hi);
        if (!flo && !fhi)      { lo = -1.0f; hi = 1.0f; }
        else if (!flo)         lo = hi - 2.0f;
        else if (!fhi)         hi = lo + 2.0f;
        reps[t] = 0.5f * (lo + hi);
    }
    __syncthreads();
    if (t < HID) g_us[t] = us[t];
    for (int e = t; e < CH * 17; e += blockDim.x) {
        int c = e / 17, i = e - c * 17;
        float rep = reps[i];
        float a = 0.0f, bb = b2[c];
        #pragma unroll
        for (int k = 0; k < HID; k++) {
            float wk = w1[k], bk = b1[k];
            if (fmaf(rep, wk, bk) > 0.0f) {      // hidden unit k active on interval i?
                float wv = w2[c * HID + k];
                a  = fmaf(wv, wk, a);
                bb = fmaf(wv, bk, bb);
            }
        }
        g_AB[e] = make_float2(a, bb);
    }
}

__global__ __launch_bounds__(TPB, 6)
void pse_main_kernel(const float4* __restrict__ x, float4* __restrict__ out)
{
    __shared__ float4 red4[NGRP * P4];   // 4 KB
    __shared__ float4 s4b[P4];
    __shared__ int4   i4b[P4];

    const int t = threadIdx.x;
    const int q = t & (P4 - 1);          // float4-pixel 0..15
    const int g = t >> 4;                // channel group 0..15

    const int tile  = blockIdx.x;
    const int img   = tile >> 6;         // 64 tiles per image
    const int base4 = (tile & 63) << 4;

    const float4* xb = x   + (size_t)img * CH * HW4 + base4;
    float4*       ob = out + (size_t)img * CH * HW4 + base4;

    // ---- pass 1: channel-partial sums (DRAM read; no table dependency) ----
    float4 s = make_float4(0.f, 0.f, 0.f, 0.f);
    #pragma unroll 8
    for (int j = 0; j < CPT; j++) {
        const float4 v = __ldg(&xb[(g + j * NGRP) * HW4 + q]);
        s.x += v.x; s.y += v.y; s.z += v.z; s.w += v.w;
    }
    red4[g * P4 + q] = s;

    // Table build (prior kernel) must be complete before we read g_us/g_AB.
    cudaGridDependencySynchronize();
    __syncthreads();

    // ---- reduce + interval classification (16 threads) ----
    if (t < P4) {
        float4 acc = red4[t];
        #pragma unroll
        for (int g2 = 1; g2 < NGRP; g2++) {
            float4 r = red4[g2 * P4 + t];
            acc.x += r.x; acc.y += r.y; acc.z += r.z; acc.w += r.w;
        }
        const float inv = 1.0f / (float)CH;
        float4 sv = make_float4(acc.x * inv, acc.y * inv, acc.z * inv, acc.w * inv);
        int4 iv = make_int4(0, 0, 0, 0);
        #pragma unroll
        for (int k = 0; k < HID; k++) {
            const float tk = g_us[k];
            iv.x += (sv.x > tk); iv.y += (sv.y > tk);
            iv.z += (sv.z > tk); iv.w += (sv.w > tk);
        }
        s4b[t] = sv; i4b[t] = iv;
    }
    __syncthreads();

    // ---- pass 2: re-read x (L2 hit), z = A*s+B, out = x*sigmoid(z) ----
    const float4 sv = s4b[q];
    const int4   iv = i4b[q];
    #pragma unroll 2
    for (int j = 0; j < CPT; j++) {
        const int c = g + j * NGRP;
        const float4 v = __ldcs(&xb[c * HW4 + q]);     // dead after this use
        const float2* row = g_AB + c * 17;             // 34KB table: L1-resident
        const float2 a0 = row[iv.x], a1 = row[iv.y],
                     a2 = row[iv.z], a3 = row[iv.w];
        const float z0 = fmaf(a0.x, sv.x, a0.y);
        const float z1 = fmaf(a1.x, sv.y, a1.y);
        const float z2 = fmaf(a2.x, sv.z, a2.y);
        const float z3 = fmaf(a3.x, sv.w, a3.y);
        float4 o;
        o.x = __fdividef(v.x, 1.0f + __expf(-z0));
        o.y = __fdividef(v.y, 1.0f + __expf(-z1));
        o.z = __fdividef(v.z, 1.0f + __expf(-z2));
        o.w = __fdividef(v.w, 1.0f + __expf(-z3));
        __stcs(&ob[c * HW4 + q], o);                   // never re-read
    }
}

extern "C" void kernel_launch(void* const* d_in, const int* in_sizes, int n_in,
                              void* d_out, int out_size)
{
    const float*  w1 = (const float*)d_in[1];
    const float*  b1 = (const float*)d_in[2];
    const float*  w2 = (const float*)d_in[3];
    const float*  b2 = (const float*)d_in[4];

    build_table_kernel<<<1, 256>>>(w1, b1, w2, b2);

    // Main kernel with programmatic dependent launch: starts while
    // build_table runs; synchronizes in-kernel before consuming the table.
    cudaLaunchAttribute attrs[1];
    attrs[0].id = cudaLaunchAttributeProgrammaticStreamSerialization;
    attrs[0].val.programmaticStreamSerializationAllowed = 1;

    cudaLaunchConfig_t cfg = {};
    cfg.gridDim  = dim3(NTILE);
    cfg.blockDim = dim3(TPB);
    cfg.dynamicSmemBytes = 0;
    cfg.stream = 0;
    cfg.attrs = attrs;
    cfg.numAttrs = 1;

    const float4* xv = (const float4*)d_in[0];
    float4* ov = (float4*)d_out;
    cudaLaunchKernelEx(&cfg, pse_main_kernel, xv, ov);
}

// round 5
// speedup vs baseline: 2.3778x; 1.2691x over previous
#include <cuda_runtime.h>
#include <math.h>

// x (B=32, C=256, H=64, W=64) fp32; s=mean_c(x); h=relu(s*w1+b1)[16];
// scale=sigmoid(w2@h+b2); out=x*scale
// Identity: z[c] = w2[c]@relu(s*w1+b1)+b2[c] is piecewise-linear in s:
//   z[c] = A[c,i]*s + B[c,i],  i = #{k : s > t_k},  t_k = -b1[k]/w1[k]
// R5: ONE persistent kernel. Each CTA builds the (A,B) table in smem once,
// then loops tiles. x is held in REGISTERS across the mean-reduce barriers
// (no L2 re-read). 512 thr, 8 float4/thread, 2 CTAs/SM.

#define B_    32
#define CH    256
#define HW4   1024          // 4096/4 float4 per (b,c) row
#define HID   16
#define P4    16            // float4 pixels per tile (64 px)
#define TPB   512
#define NGRP  32            // TPB / P4 channel groups
#define CPT   8             // CH / NGRP channels per thread (x regs = 32)
#define NTILE 2048          // 32 images * (4096/64) tiles
#define GRID  296           // 2 persistent CTAs per SM * 148

__global__ __launch_bounds__(TPB, 2)
void pse_fused_kernel(const float4* __restrict__ x,
                      const float*  __restrict__ w1,
                      const float*  __restrict__ b1,
                      const float*  __restrict__ w2,
                      const float*  __restrict__ b2,
                      float4* __restrict__ out)
{
    __shared__ float2 AB[CH * 17];        // 34,816 B piecewise-linear table
    __shared__ float4 red4[NGRP * P4];    //  8,192 B partial sums
    __shared__ float4 s4b[P4];
    __shared__ int4   i4b[P4];
    __shared__ float  us[HID];            // sorted thresholds
    __shared__ float  reps[HID + 1];

    const int t = threadIdx.x;
    const int q = t & (P4 - 1);           // float4-pixel 0..15
    const int g = t >> 4;                 // channel group 0..31
    const float INF = __int_as_float(0x7f800000);

    // ---------- per-CTA prologue: build piecewise-linear table ----------
    if (t < HID) {
        float w = w1[t], b = b1[t];
        float myth = (w != 0.0f) ? (-b / w) : INF;
        int rank = 0;
        #pragma unroll
        for (int k = 0; k < HID; k++) {
            float wk = w1[k], bk = b1[k];
            float tk = (wk != 0.0f) ? (-bk / wk) : INF;
            rank += (tk < myth) || (tk == myth && k < t);
        }
        us[rank] = myth;
    }
    __syncthreads();
    if (t < HID + 1) {
        float lo = (t == 0)   ? -INF : us[t - 1];
        float hi = (t == HID) ?  INF : us[t];
        bool flo = isfinite(lo), fhi = isfinite(hi);
        if (!flo && !fhi)      { lo = -1.0f; hi = 1.0f; }
        else if (!flo)         lo = hi - 2.0f;
        else if (!fhi)         hi = lo + 2.0f;
        reps[t] = 0.5f * (lo + hi);
    }
    __syncthreads();
    if (t < CH) {
        const int c = t;
        float w2r[HID];
        #pragma unroll
        for (int k = 0; k < HID; k++) w2r[k] = w2[c * HID + k];
        const float bc = b2[c];
        for (int i = 0; i < 17; i++) {
            const float rep = reps[i];
            float a = 0.0f, bb = bc;
            #pragma unroll
            for (int k = 0; k < HID; k++) {
                float wk = w1[k], bk = b1[k];
                if (fmaf(rep, wk, bk) > 0.0f) {   // unit k active on interval i
                    a  = fmaf(w2r[k], wk, a);
                    bb = fmaf(w2r[k], bk, bb);
                }
            }
            AB[c * 17 + i] = make_float2(a, bb);
        }
    }
    __syncthreads();

    // ---------- persistent tile loop ----------
    for (int tile = blockIdx.x; tile < NTILE; tile += GRID) {
        const int img   = tile >> 6;          // 64 tiles per image
        const int base4 = (tile & 63) << 4;
        const float4* xb = x   + (size_t)img * CH * HW4 + base4;
        float4*       ob = out + (size_t)img * CH * HW4 + base4;

        // pass 1: 8 independent LDG.128 into REGISTERS (kept live), + sums
        float4 v[CPT];
        #pragma unroll
        for (int j = 0; j < CPT; j++)
            v[j] = __ldcs(&xb[(g + j * NGRP) * HW4 + q]);   // read-once data

        float4 s = make_float4(0.f, 0.f, 0.f, 0.f);
        #pragma unroll
        for (int j = 0; j < CPT; j++) {
            s.x += v[j].x; s.y += v[j].y; s.z += v[j].z; s.w += v[j].w;
        }
        red4[g * P4 + q] = s;
        __syncthreads();

        // reduce 32 partials -> mean; classify interval per pixel (16 threads)
        if (t < P4) {
            float4 acc = red4[t];
            #pragma unroll
            for (int g2 = 1; g2 < NGRP; g2++) {
                float4 r = red4[g2 * P4 + t];
                acc.x += r.x; acc.y += r.y; acc.z += r.z; acc.w += r.w;
            }
            const float inv = 1.0f / (float)CH;
            float4 sv = make_float4(acc.x*inv, acc.y*inv, acc.z*inv, acc.w*inv);
            int4 iv = make_int4(0, 0, 0, 0);
            #pragma unroll
            for (int k = 0; k < HID; k++) {
                const float tk = us[k];
                iv.x += (sv.x > tk); iv.y += (sv.y > tk);
                iv.z += (sv.z > tk); iv.w += (sv.w > tk);
            }
            s4b[t] = sv; i4b[t] = iv;
        }
        __syncthreads();

        // pass 2: pure compute from registers + smem table, then store
        const float4 sv = s4b[q];
        const int4   iv = i4b[q];
        #pragma unroll
        for (int j = 0; j < CPT; j++) {
            const int c = g + j * NGRP;
            const float2* row = AB + c * 17;
            const float2 a0 = row[iv.x], a1 = row[iv.y],
                         a2 = row[iv.z], a3 = row[iv.w];
            const float z0 = fmaf(a0.x, sv.x, a0.y);
            const float z1 = fmaf(a1.x, sv.y, a1.y);
            const float z2 = fmaf(a2.x, sv.z, a2.y);
            const float z3 = fmaf(a3.x, sv.w, a3.y);
            float4 o;
            o.x = __fdividef(v[j].x, 1.0f + __expf(-z0));
            o.y = __fdividef(v[j].y, 1.0f + __expf(-z1));
            o.z = __fdividef(v[j].z, 1.0f + __expf(-z2));
            o.w = __fdividef(v[j].w, 1.0f + __expf(-z3));
            __stcs(&ob[c * HW4 + q], o);                    // never re-read
        }
        // next iteration's red4/s4b writes are fenced by its __syncthreads()
    }
}

extern "C" void kernel_launch(void* const* d_in, const int* in_sizes, int n_in,
                              void* d_out, int out_size)
{
    pse_fused_kernel<<<GRID, TPB>>>((const float4*)d_in[0],
                                    (const float*)d_in[1],
                                    (const float*)d_in[2],
                                    (const float*)d_in[3],
                                    (const float*)d_in[4],
                                    (float4*)d_out);
}